// round 1
// baseline (speedup 1.0000x reference)
#include <cuda_runtime.h>

#define NC   14
#define H    2048
#define W    2048
#define TILE 32
#define HD   34          // tile + halo
#define STR  36          // padded smem row stride (floats), 16B multiple
#define GB   64          // blocks per grid dim
#define NBLK (GB * GB)

// Per-block, per-channel partials (written once per block, fixed slots -> deterministic)
__device__ float g_min[NC * NBLK];
__device__ float g_sum[NC * NBLK];
__device__ float g_cnt[NC * NBLK];
__device__ float g_t1 [NC * NBLK];
__device__ float g_t2 [NC * NBLK];
__device__ float g_loss[NC];

extern __shared__ float sp[];   // [NC][HD][STR] probs

__device__ __forceinline__ float* SP(int ch, int r) {
    return sp + (ch * HD + r) * STR;
}

__global__ __launch_bounds__(256, 2)
void tile_kernel(const float* __restrict__ in) {
    __shared__ float sred[8][4][5];   // [warp][channel-slot][min,sum,cnt,t1,t2]

    const int tid = threadIdx.y * 64 + threadIdx.x;
    const int x0 = blockIdx.x * TILE - 1;
    const int y0 = blockIdx.y * TILE - 1;

    // ---- Phase 1: load logits (tile+halo), softmax across 14 channels, stash probs in smem
    for (int i = tid; i < HD * HD; i += 256) {
        int r = i / HD;
        int c = i - r * HD;
        int gy = y0 + r, gx = x0 + c;
        if ((unsigned)gy < H && (unsigned)gx < W) {
            const float* g = in + gy * W + gx;
            float e[NC];
            float m = -1e30f;
            #pragma unroll
            for (int ch = 0; ch < NC; ch++) {
                e[ch] = g[ch * (H * W)];
                m = fmaxf(m, e[ch]);
            }
            float d = 0.f;
            #pragma unroll
            for (int ch = 0; ch < NC; ch++) {
                e[ch] = __expf(e[ch] - m);
                d += e[ch];
            }
            float rd = 1.0f / d;
            #pragma unroll
            for (int ch = 0; ch < NC; ch++)
                SP(ch, r)[c] = e[ch] * rd;
        } else {
            // outside image: acts like -inf padding (all probs > 0 > -1)
            #pragma unroll
            for (int ch = 0; ch < NC; ch++)
                SP(ch, r)[c] = -1.0f;
        }
    }
    __syncthreads();

    // ---- Phase 2: per-channel strict local maxima + partial stats
    // thread layout: threadIdx.y = z (channel group), threadIdx.x: sx(3b)=col-group, sy=row-group
    const int z  = threadIdx.y;          // 0..3  -> channels z, z+4, z+8, z+12
    const int sx = threadIdx.x & 7;      // 0..7  -> cols 4*sx .. 4*sx+3 (interior)
    const int sy = threadIdx.x >> 3;     // 0..7  -> rows 4*sy .. 4*sy+3 (interior)
    const int cb = 4 * sx;               // smem col base (covers cb..cb+5)
    const int rb = 4 * sy;               // smem row base (covers rb..rb+5)

    float amin[4], asum[4], acnt[4], at1[4], at2[4];
    #pragma unroll
    for (int s = 0; s < 4; s++) {
        amin[s] = 1e30f; asum[s] = 0.f; acnt[s] = 0.f;
        at1[s] = -1e30f; at2[s] = -1e30f;
    }

    #pragma unroll
    for (int s = 0; s < 4; s++) {
        int ch = z + 4 * s;
        if (ch < NC) {   // uniform per warp (warp = single z) -> no divergence
            float v[6][6];
            #pragma unroll
            for (int j = 0; j < 6; j++) {
                const float* row = SP(ch, rb + j) + cb;
                float4 a = *(const float4*)row;          // 16B-aligned (STR%4==0, cb%4==0)
                float2 b = *(const float2*)(row + 4);
                v[j][0] = a.x; v[j][1] = a.y; v[j][2] = a.z; v[j][3] = a.w;
                v[j][4] = b.x; v[j][5] = b.y;
            }
            // separable horizontal max-of-3
            float m3[6][4];
            #pragma unroll
            for (int j = 0; j < 6; j++)
                #pragma unroll
                for (int i = 0; i < 4; i++)
                    m3[j][i] = fmaxf(fmaxf(v[j][i], v[j][i + 1]), v[j][i + 2]);

            #pragma unroll
            for (int j = 1; j <= 4; j++) {
                #pragma unroll
                for (int i = 0; i < 4; i++) {
                    float p  = v[j][i + 1];
                    float nb = fmaxf(fmaxf(m3[j - 1][i], m3[j + 1][i]),
                                     fmaxf(v[j][i], v[j][i + 2]));
                    amin[s] = fminf(amin[s], p);
                    if (p > nb) {                 // strict 8-neighbor local max
                        asum[s] += p;
                        acnt[s] += 1.f;
                        if (p > at1[s]) { at2[s] = at1[s]; at1[s] = p; }
                        else if (p > at2[s]) { at2[s] = p; }
                    }
                }
            }
        }
    }

    // ---- Phase 3: warp reduction (warp == one z-group half: 32 threads, same channels)
    #pragma unroll
    for (int off = 16; off > 0; off >>= 1) {
        #pragma unroll
        for (int s = 0; s < 4; s++) {
            amin[s] = fminf(amin[s], __shfl_down_sync(0xffffffffu, amin[s], off));
            asum[s] += __shfl_down_sync(0xffffffffu, asum[s], off);
            acnt[s] += __shfl_down_sync(0xffffffffu, acnt[s], off);
            float b1 = __shfl_down_sync(0xffffffffu, at1[s], off);
            float b2 = __shfl_down_sync(0xffffffffu, at2[s], off);
            float lo = fminf(at1[s], b1);
            at1[s] = fmaxf(at1[s], b1);
            at2[s] = fmaxf(lo, fmaxf(at2[s], b2));
        }
    }
    const int warp = tid >> 5;
    const int lane = tid & 31;
    if (lane == 0) {
        #pragma unroll
        for (int s = 0; s < 4; s++) {
            sred[warp][s][0] = amin[s];
            sred[warp][s][1] = asum[s];
            sred[warp][s][2] = acnt[s];
            sred[warp][s][3] = at1[s];
            sred[warp][s][4] = at2[s];
        }
    }
    __syncthreads();

    // combine the two warps of each z-group, write block partials
    if (tid < NC) {
        int c  = tid;
        int zz = c & 3, ss = c >> 2;
        int w0 = 2 * zz, w1 = 2 * zz + 1;
        float mn = fminf(sred[w0][ss][0], sred[w1][ss][0]);
        float sm = sred[w0][ss][1] + sred[w1][ss][1];
        float ct = sred[w0][ss][2] + sred[w1][ss][2];
        float a1 = sred[w0][ss][3], a2 = sred[w0][ss][4];
        float b1 = sred[w1][ss][3], b2 = sred[w1][ss][4];
        float lo = fminf(a1, b1);
        float t1 = fmaxf(a1, b1);
        float t2 = fmaxf(lo, fmaxf(a2, b2));
        int bid = blockIdx.y * GB + blockIdx.x;
        int idx = c * NBLK + bid;
        g_min[idx] = mn; g_sum[idx] = sm; g_cnt[idx] = ct;
        g_t1[idx]  = t1; g_t2[idx]  = t2;
    }
}

__global__ void reduce_kernel() {
    const int c = blockIdx.x;
    const int tid = threadIdx.x;
    float mn = 1e30f, sm = 0.f, ct = 0.f, t1 = -1e30f, t2 = -1e30f;
    for (int i = tid; i < NBLK; i += 256) {
        int idx = c * NBLK + i;
        mn = fminf(mn, g_min[idx]);
        sm += g_sum[idx];
        ct += g_cnt[idx];
        float b1 = g_t1[idx], b2 = g_t2[idx];
        float lo = fminf(t1, b1);
        t1 = fmaxf(t1, b1);
        t2 = fmaxf(lo, fmaxf(t2, b2));
    }
    #pragma unroll
    for (int off = 16; off > 0; off >>= 1) {
        mn = fminf(mn, __shfl_down_sync(0xffffffffu, mn, off));
        sm += __shfl_down_sync(0xffffffffu, sm, off);
        ct += __shfl_down_sync(0xffffffffu, ct, off);
        float b1 = __shfl_down_sync(0xffffffffu, t1, off);
        float b2 = __shfl_down_sync(0xffffffffu, t2, off);
        float lo = fminf(t1, b1);
        t1 = fmaxf(t1, b1);
        t2 = fmaxf(lo, fmaxf(t2, b2));
    }
    __shared__ float s[8][5];
    int warp = tid >> 5, lane = tid & 31;
    if (lane == 0) { s[warp][0]=mn; s[warp][1]=sm; s[warp][2]=ct; s[warp][3]=t1; s[warp][4]=t2; }
    __syncthreads();
    if (tid == 0) {
        mn = s[0][0]; sm = s[0][1]; ct = s[0][2]; t1 = s[0][3]; t2 = s[0][4];
        #pragma unroll
        for (int w = 1; w < 8; w++) {
            mn = fminf(mn, s[w][0]); sm += s[w][1]; ct += s[w][2];
            float b1 = s[w][3], b2 = s[w][4];
            float lo = fminf(t1, b1);
            t1 = fmaxf(t1, b1);
            t2 = fmaxf(lo, fmaxf(t2, b2));
        }
        // channel loss: imp = p - min; total = sum(imp over maxima);
        // top-k hinge + spurious-mass penalty
        float total = sm - ct * mn;
        float v1 = t1 - mn, v2 = t2 - mn;
        int k = (c < 7) ? 1 : 2;
        float target = 0.f, hinge = 0.f;
        if (ct >= 1.f)             { target += v1; hinge += fmaxf(0.f, 1.f - v1); }
        if (k == 2 && ct >= 2.f)   { target += v2; hinge += fmaxf(0.f, 1.f - v2); }
        g_loss[c] = (total - target) + hinge;
    }
}

__global__ void final_kernel(float* __restrict__ out) {
    if (threadIdx.x == 0 && blockIdx.x == 0) {
        float s = 0.f;
        #pragma unroll
        for (int c = 0; c < NC; c++) s += g_loss[c];
        out[0] = s / (float)NC;
    }
}

extern "C" void kernel_launch(void* const* d_in, const int* in_sizes, int n_in,
                              void* d_out, int out_size) {
    const float* in = (const float*)d_in[0];   // [1,14,2048,2048] f32 logits
    // d_in[1] = target (int64) — unused by the loss
    float* out = (float*)d_out;

    const size_t smem = (size_t)NC * HD * STR * sizeof(float);   // 68544 B
    cudaFuncSetAttribute(tile_kernel, cudaFuncAttributeMaxDynamicSharedMemorySize, (int)smem);

    dim3 grid(GB, GB), block(64, 4);
    tile_kernel<<<grid, block, smem>>>(in);
    reduce_kernel<<<NC, 256>>>();
    final_kernel<<<1, 32>>>(out);
}